// round 16
// baseline (speedup 1.0000x reference)
#include <cuda_runtime.h>
#include <math.h>

// Problem constants
#define HH 768
#define WW 768
#define NIMG 32
#define HWI (768 * 768)
#define HWLL (768LL * 768LL)

#define TW 128                 // columns per tile
#define ROWS 16                // rows per warp
#define KTOT 20                // rows loaded per warp (ROWS + 4 halo)
#define TILE_H 64              // 4 warps/CTA
#define TPI 72                 // tiles per image (6 x 12)
#define NT (NIMG * TPI)        // 2304 total tiles
#define NCTA 592               // 148 SMs x 4 CTAs — all resident

#define MIN_WEIGHT 0.1f

__device__ float g_part[NIMG * TPI];
__device__ float g_scale[NIMG];
__device__ int   g_done[NIMG];
__device__ int   g_rdy[NIMG];
__device__ int   g_ctr, g_ctr2;

__global__ void k_init() {
    const int t = threadIdx.x;
    if (t < NIMG) { g_done[t] = 0; g_rdy[t] = 0; }
    if (t == 32) g_ctr = 0;
    if (t == 33) g_ctr2 = 0;
}

__device__ __forceinline__ float tanh_a(float x) {
    float r;
    asm("tanh.approx.f32 %0, %1;" : "=f"(r) : "f"(x));
    return r;
}
__device__ __forceinline__ float sigm(float x) {
    return fmaf(0.5f, tanh_a(0.5f * x), 0.5f);
}

#define LOADROW(kk, INB, Y, H0, H1)                                             \
{                                                                               \
    const int gr = gi0 + (kk) - 2;                                              \
    Y = make_float4(0.f, 0.f, 0.f, 0.f); H0 = 0.f; H1 = 0.f;                    \
    if ((INB) || (unsigned)gr < (unsigned)HH) {                                 \
        Y = *reinterpret_cast<const float4*>(yimg + gr * WW + gj0);             \
        if (eL & hasL) {                                                        \
            float2 t = *reinterpret_cast<const float2*>(yimg + gr * WW + col0 - 2); \
            H0 = t.x; H1 = t.y;                                                 \
        }                                                                       \
        if (eR & hasR) {                                                        \
            float2 t = *reinterpret_cast<const float2*>(yimg + gr * WW + col0 + TW); \
            H0 = t.x; H1 = t.y;                                                 \
        }                                                                       \
    }                                                                           \
}

#define PROCROW(kk, INB, Y, H0, H1)                                             \
{                                                                               \
    const int gr = gi0 + (kk) - 2;                                              \
    float4 p; float lz, lw, rx, ry;                                             \
    if ((INB) || (unsigned)gr < (unsigned)HH) {                                 \
        p.x = sigm(Y.x); p.y = sigm(Y.y); p.z = sigm(Y.z); p.w = sigm(Y.w);     \
        const float s0 = sigm(H0), s1 = sigm(H1);                               \
        lz = __shfl_up_sync(0xffffffffu, p.z, 1);                               \
        lw = __shfl_up_sync(0xffffffffu, p.w, 1);                               \
        rx = __shfl_down_sync(0xffffffffu, p.x, 1);                             \
        ry = __shfl_down_sync(0xffffffffu, p.y, 1);                             \
        if (eL) { lz = hasL ? s0 : 0.f; lw = hasL ? s1 : 0.f; }                 \
        if (eR) { rx = hasR ? s0 : 0.f; ry = hasR ? s1 : 0.f; }                 \
    } else {                                                                    \
        p = make_float4(0.f, 0.f, 0.f, 0.f); lz = lw = rx = ry = 0.f;           \
    }                                                                           \
    float4 hs, hq;                                                              \
    hs.x = lz + lw + p.x + p.y + p.z;                                           \
    hs.y = hs.x - lz + p.w;                                                     \
    hs.z = hs.y - lw + rx;                                                      \
    hs.w = hs.z - p.x + ry;                                                     \
    const float qlz = lz*lz, qlw = lw*lw, qx = p.x*p.x, qy = p.y*p.y;           \
    const float qz = p.z*p.z, qw = p.w*p.w, qrx = rx*rx, qry = ry*ry;           \
    hq.x = qlz + qlw + qx + qy + qz;                                            \
    hq.y = hq.x - qlz + qw;                                                     \
    hq.z = hq.y - qlw + qrx;                                                    \
    hq.w = hq.z - qx + qry;                                                     \
    S.x += hs.x - hsR[(kk) % 5].x;  S.y += hs.y - hsR[(kk) % 5].y;              \
    S.z += hs.z - hsR[(kk) % 5].z;  S.w += hs.w - hsR[(kk) % 5].w;              \
    Q.x += hq.x - hqR[(kk) % 5].x;  Q.y += hq.y - hqR[(kk) % 5].y;              \
    Q.z += hq.z - hqR[(kk) % 5].z;  Q.w += hq.w - hqR[(kk) % 5].w;              \
    hsR[(kk) % 5] = hs;  hqR[(kk) % 5] = hq;                                    \
    pR[(kk) % 3] = p;                                                           \
}

__global__ __launch_bounds__(128, 4) void k_persist(
    const float* __restrict__ yd,
    const float* __restrict__ ygt,
    float* __restrict__ out)
{
    __shared__ int   s_cmd, s_tile;
    __shared__ float wsum[4];

    const int tid  = threadIdx.x;
    const int lane = tid & 31;
    const int wrp  = tid >> 5;
    const bool eL = (lane == 0), eR = (lane == 31);

    for (;;) {
        if (tid == 0) {
            int cmd = -1, tl = -1;
            // prefer a READY rescale tile (CAS-pop, never blocks)
            int cur = *(volatile int*)&g_ctr2;
            if (cur < NT && *(volatile int*)&g_rdy[cur / TPI]) {
                if (atomicCAS(&g_ctr2, cur, cur + 1) == cur) { cmd = 1; tl = cur; }
            }
            if (cmd < 0) {
                int t = atomicAdd(&g_ctr, 1);
                if (t < NT) { cmd = 0; tl = t; }
            }
            if (cmd < 0) {
                int t2 = atomicAdd(&g_ctr2, 1);
                if (t2 < NT) {
                    cmd = 1; tl = t2;
                    volatile int* r = &g_rdy[t2 / TPI];
                    while (!*r) __nanosleep(100);   // setter is in-flight compute
                } else cmd = 2;
            }
            s_cmd = cmd; s_tile = tl;
        }
        __syncthreads();
        const int cmd = s_cmd;
        const int t   = s_tile;
        __syncthreads();
        if (cmd == 2) break;

        const int img = t / TPI;
        const int tl  = t - img * TPI;
        const int bx  = tl % 6;
        const int by  = tl / 6;
        const int col0 = bx * TW;
        const int gj0  = col0 + lane * 4;
        float* __restrict__ oimg = out + (long long)img * HWLL;

        if (cmd == 0) {
            // ================= COMPUTE tile =================
            const int chunk = by * 4 + wrp;
            const int gi0   = chunk * ROWS;
            const float* __restrict__ yimg = yd  + (long long)img * HWLL;
            const float* __restrict__ gimg = ygt + (long long)img * HWLL;
            const bool hasL = (col0 > 0), hasR = (col0 + TW < WW);

            float fcx[4], rinvI[4];
            #pragma unroll
            for (int m = 0; m < 4; ++m) {
                const int gj = gj0 + m;
                fcx[m]   = (float)(min(gj, 2) + min(WW - 1 - gj, 2) + 1);
                rinvI[m] = __fdividef(1.0f, fcx[m] * 5.0f - 1.0f);
            }

            float4 hsR[5], hqR[5], pR[3];
            #pragma unroll
            for (int i = 0; i < 5; ++i) {
                hsR[i] = make_float4(0.f, 0.f, 0.f, 0.f);
                hqR[i] = make_float4(0.f, 0.f, 0.f, 0.f);
            }
            float4 S = make_float4(0.f, 0.f, 0.f, 0.f);
            float4 Q = make_float4(0.f, 0.f, 0.f, 0.f);

            float lsum = 0.0f;
            float4 yc, yn; float hc0, hc1, hn0, hn1;
            LOADROW(0, false, yc, hc0, hc1)

            #pragma unroll
            for (int k = 0; k < KTOT; ++k) {
                if (k + 1 < KTOT) {
                    LOADROW(k + 1, ((k + 1) >= 2) && ((k + 1) <= KTOT - 3), yn, hn0, hn1)
                }
                float4 gv;
                if (k >= 4)
                    gv = *reinterpret_cast<const float4*>(gimg + (gi0 + k - 4) * WW + gj0);

                PROCROW(k, (k >= 2) && (k <= KTOT - 3), yc, hc0, hc1)

                if (k >= 4) {
                    const int gro = gi0 + k - 4;
                    const float4 P0 = pR[(k - 2) % 3];
                    const bool  yin = (gro >= 2) & (gro < HH - 2);
                    const float fcy = yin ? 5.0f
                                          : (float)(min(gro, 2) + min(HH - 1 - gro, 2) + 1);
                    float4 w;
                    #define DO_COMP(c, mi)                                      \
                    {                                                           \
                        const float fnv  = fcx[mi] * fcy;                       \
                        const float rinv = yin ? rinvI[mi]                      \
                                               : __fdividef(1.0f, fnv - 1.0f);  \
                        const float p0  = P0.c;                                 \
                        const float acc = fmaf(fmaf(fnv, p0, -2.0f * S.c), p0, Q.c); \
                        const float cons = 1.0f - acc * rinv;                   \
                        const float qq  = 1.0f - p0;                            \
                        const float l2p = __log2f(fmaxf(p0, 1e-37f));           \
                        const float l2q = __log2f(fmaxf(qq, 1e-37f));           \
                        const float ent = fmaf(p0, l2p, fmaf(qq, l2q, 1.0f));   \
                        float ww = fmaxf(cons * ent, gv.c);                     \
                        w.c = fmaf(1.0f - MIN_WEIGHT, ww, MIN_WEIGHT);          \
                    }
                    DO_COMP(x, 0)
                    DO_COMP(y, 1)
                    DO_COMP(z, 2)
                    DO_COMP(w, 3)
                    #undef DO_COMP

                    *reinterpret_cast<float4*>(oimg + gro * WW + gj0) = w;  // unscaled
                    lsum += (w.x + w.y) + (w.z + w.w);
                }
                yc = yn; hc0 = hn0; hc1 = hn1;
            }

            #pragma unroll
            for (int o = 16; o; o >>= 1) lsum += __shfl_down_sync(0xffffffffu, lsum, o);
            if (lane == 0) wsum[wrp] = lsum;
            __syncthreads();

            if (wrp == 0) {
                int old = 0;
                if (lane == 0) {
                    g_part[img * TPI + tl] = wsum[0] + wsum[1] + wsum[2] + wsum[3];
                    __threadfence();
                    old = atomicAdd(&g_done[img], 1);
                }
                old = __shfl_sync(0xffffffffu, old, 0);
                if (old == TPI - 1) {
                    // last tile of this image: reduce 72 partials, publish scale
                    __threadfence();
                    float v = 0.0f;
                    #pragma unroll
                    for (int b = 0; b < 3; ++b) {
                        const int idx = lane + b * 32;
                        if (idx < TPI) v += g_part[img * TPI + idx];
                    }
                    #pragma unroll
                    for (int o = 16; o; o >>= 1) v += __shfl_down_sync(0xffffffffu, v, o);
                    if (lane == 0) {
                        g_scale[img] = __fdividef((float)HWI, v);
                        __threadfence();
                        g_rdy[img] = 1;
                    }
                }
            }
        } else {
            // ================= RESCALE tile =================
            float s;
            asm volatile("ld.global.cg.f32 %0, [%1];" : "=f"(s) : "l"(g_scale + img));
            const int r0 = by * TILE_H + wrp * ROWS;
            #pragma unroll
            for (int o = 0; o < ROWS; ++o) {
                float* addr = oimg + (r0 + o) * WW + gj0;
                float4 w;
                asm volatile("ld.global.cg.v4.f32 {%0,%1,%2,%3}, [%4];"
                             : "=f"(w.x), "=f"(w.y), "=f"(w.z), "=f"(w.w)
                             : "l"(addr));
                w.x *= s; w.y *= s; w.z *= s; w.w *= s;
                *reinterpret_cast<float4*>(addr) = w;
            }
        }
    }
}

extern "C" void kernel_launch(void* const* d_in, const int* in_sizes, int n_in,
                              void* d_out, int out_size) {
    const float* yd  = (const float*)d_in[0];
    const float* ygt = (const float*)d_in[1];
    float* out = (float*)d_out;

    k_init<<<1, 64>>>();
    k_persist<<<NCTA, 128>>>(yd, ygt, out);
}